// round 14
// baseline (speedup 1.0000x reference)
#include <cuda_runtime.h>
#include <math.h>
#include <cstdint>

// Problem constants
#define BATCH   2
#define SEQ     2048
#define HEADS   16
#define IN_D    1024
#define MROWS   (BATCH*SEQ)       // 4096
#define FOLD    512               // folded width

// Scratch (device globals; no allocation allowed)
__device__ __align__(256) float g_XQf [MROWS*FOLD];     // folded+rope'd Q
__device__ __align__(256) float g_XKHL[MROWS*FOLD*2];   // rope'd K interleaved (hi,lo)
__device__ __align__(256) float g_XV  [MROWS*FOLD];     // V
__device__ __align__(256) float g_CTX [MROWS*FOLD];     // attention ctx
__device__ __align__(256) float g_WoF [FOLD*IN_D];      // folded Wo
__device__ float g_theta[768];                           // Q pair thetas | K pair thetas

// ---------------------------------------------------------------------------
// Helpers
// ---------------------------------------------------------------------------
__device__ __forceinline__ uint32_t smem_u32(const void* p) {
    uint32_t a;
    asm("{ .reg .u64 t; cvta.to.shared.u64 t, %1; cvt.u32.u64 %0, t; }" : "=r"(a) : "l"(p));
    return a;
}

// Truncation hi/lo split for 3xTF32 (proven numerics).
__device__ __forceinline__ void split_hl(float x, uint32_t& h, uint32_t& l) {
    h = __float_as_uint(x) & 0xFFFFE000u;
    l = __float_as_uint(x - __uint_as_float(h));
}
__device__ __forceinline__ void split_hl_f(float x, float& h, float& l) {
    h = __uint_as_float(__float_as_uint(x) & 0xFFFFE000u);
    l = x - h;
}

__device__ __forceinline__ void mma_tf32(float* d, const uint32_t* a, const uint32_t* b) {
    asm volatile(
        "mma.sync.aligned.m16n8k8.row.col.f32.tf32.tf32.f32 "
        "{%0,%1,%2,%3}, {%4,%5,%6,%7}, {%8,%9}, {%0,%1,%2,%3};"
        : "+f"(d[0]), "+f"(d[1]), "+f"(d[2]), "+f"(d[3])
        : "r"(a[0]), "r"(a[1]), "r"(a[2]), "r"(a[3]), "r"(b[0]), "r"(b[1]));
}

// fast 2^t on the FMA/ALU pipes (proven).
__device__ __forceinline__ float exp2fast(float t) {
    float z = t + 12582912.0f;                 // 1.5*2^23
    int   n = __float_as_int(z) - 0x4B400000;
    float f = t - (z - 12582912.0f);           // f in [-0.5, 0.5]
    float r = 1.0f + f*(0.69314718f + f*(0.24022651f + f*(0.05550411f
                  + f*(0.00961813f + f*0.00133336f))));
    return __int_as_float(__float_as_int(r) + (n << 23));
}

// cp.async primitives
#define CPA16(dst, src) \
    asm volatile("cp.async.cg.shared.global [%0], [%1], 16;" :: "r"(dst), "l"(src) : "memory")
#define CP_COMMIT() asm volatile("cp.async.commit_group;" ::: "memory")
#define CP_WAIT1()  asm volatile("cp.async.wait_group 1;" ::: "memory")
#define CP_WAIT0()  asm volatile("cp.async.wait_group 0;" ::: "memory")

// Conflict-free smem strides (floats)
#define A_STR 36
#define B_STR 136
#define A_ELEMS (128 * A_STR)
#define B_ELEMS (32 * B_STR)
#define BUF_FLOATS (A_ELEMS + B_ELEMS)
#define GSMEM_BYTES (2 * BUF_FLOATS * 4)   // 71680 B

// ---------------------------------------------------------------------------
// 3xTF32 tile GEMM mainloop — EXACT R9 measured-best scheme (WAIT1 prefetch).
// CTA tile 128x128, BK=32, 256 threads (8 warps 2x4), warp tile 64x32.
// ---------------------------------------------------------------------------
__device__ __forceinline__ void gemm_mainloop(
    float* sm, uint32_t smb,
    const float* __restrict__ A, int lda,
    const float* __restrict__ B, int ldb,
    int nk, int tid, float c[4][4][4])
{
    const int wid = tid >> 5, lane = tid & 31;
    const int wm = wid & 1, wn = wid >> 1;
    const int tq = lane >> 2, tr = lane & 3;
    const int nit = nk / 32;

    auto load_tile = [&](int buf, int k0) {
        uint32_t as = smb + buf * (BUF_FLOATS * 4);
        uint32_t bs = as + A_ELEMS * 4;
        #pragma unroll
        for (int i = 0; i < 4; i++) {
            int e = i * 256 + tid;
            int r = e >> 3, c4 = e & 7;
            CPA16(as + (uint32_t)(r * A_STR + c4 * 4) * 4,
                  A + (long)r * lda + k0 + c4 * 4);
        }
        #pragma unroll
        for (int i = 0; i < 4; i++) {
            int e = i * 256 + tid;
            int kr = e >> 5, c4 = e & 31;
            CPA16(bs + (uint32_t)(kr * B_STR + c4 * 4) * 4,
                  B + (long)(k0 + kr) * ldb + c4 * 4);
        }
        CP_COMMIT();
    };

    load_tile(0, 0);
    for (int it = 0; it < nit; it++) {
        if (it + 1 < nit) { load_tile((it + 1) & 1, (it + 1) * 32); CP_WAIT1(); }
        else              { CP_WAIT0(); }
        __syncthreads();

        const float* As = sm + (it & 1) * BUF_FLOATS;
        const float* Bs = As + A_ELEMS;

        #pragma unroll
        for (int ks = 0; ks < 4; ks++) {
            uint32_t ah[4][4], al[4][4], bh[4][2], bl[4][2];
            #pragma unroll
            for (int mi = 0; mi < 4; mi++) {
                int base = (wm * 64 + mi * 16 + tq) * A_STR + ks * 8 + tr;
                split_hl(As[base],                 ah[mi][0], al[mi][0]);
                split_hl(As[base + 8 * A_STR],     ah[mi][1], al[mi][1]);
                split_hl(As[base + 4],             ah[mi][2], al[mi][2]);
                split_hl(As[base + 8 * A_STR + 4], ah[mi][3], al[mi][3]);
            }
            #pragma unroll
            for (int ni = 0; ni < 4; ni++) {
                int base = (ks * 8 + tr) * B_STR + wn * 32 + ni * 8 + tq;
                split_hl(Bs[base],             bh[ni][0], bl[ni][0]);
                split_hl(Bs[base + 4 * B_STR], bh[ni][1], bl[ni][1]);
            }
            #pragma unroll
            for (int mi = 0; mi < 4; mi++)
                #pragma unroll
                for (int ni = 0; ni < 4; ni++) {
                    mma_tf32(c[mi][ni], al[mi], bh[ni]);
                    mma_tf32(c[mi][ni], ah[mi], bl[ni]);
                    mma_tf32(c[mi][ni], ah[mi], bh[ni]);
                }
        }
        __syncthreads();
    }
}

// ---------------------------------------------------------------------------
// Kernel 1: QKV projection (3xTF32) + RoPE/fold epilogue (sincosf, R9-style).
// K written INTERLEAVED (hi,lo) for the attention kernel.
// ---------------------------------------------------------------------------
__global__ __launch_bounds__(256) void gemm_qkv(
    const float* __restrict__ A,
    const float* __restrict__ Wq,
    const float* __restrict__ Wk,
    const float* __restrict__ Wv)
{
    extern __shared__ float sm[];
    uint32_t smb = smem_u32(sm);

    const int tid = threadIdx.x;
    const int wid = tid >> 5, lane = tid & 31;
    const int wm = wid & 1, wn = wid >> 1;
    const int tq = lane >> 2, tr = lane & 3;
    const int m_base = blockIdx.y * 128;
    const int n_base = blockIdx.x * 128;

    const float* Bm; int ldb, region;
    if (n_base < 1024)      { Bm = Wq + n_base;          ldb = 1024; region = 0; }
    else if (n_base < 1536) { Bm = Wk + (n_base - 1024); ldb = 512;  region = 1; }
    else                    { Bm = Wv + (n_base - 1536); ldb = 512;  region = 2; }

    float c[4][4][4];
    #pragma unroll
    for (int i = 0; i < 4; i++)
        #pragma unroll
        for (int j = 0; j < 4; j++)
            #pragma unroll
            for (int r = 0; r < 4; r++) c[i][j][r] = 0.f;

    gemm_mainloop(sm, smb, A + (long)m_base * IN_D, IN_D, Bm, ldb, IN_D, tid, c);

    #pragma unroll
    for (int mi = 0; mi < 4; mi++) {
        #pragma unroll
        for (int h = 0; h < 2; h++) {
            const int m = m_base + wm * 64 + mi * 16 + tq + h * 8;
            const float pos = (float)((m & (SEQ - 1)) + 1);
            #pragma unroll
            for (int ni = 0; ni < 4; ni++) {
                const float xe = c[mi][ni][2 * h];
                const float xo = c[mi][ni][2 * h + 1];
                const int ncol = n_base + wn * 32 + ni * 8 + 2 * tr;
                if (region == 0) {
                    const int ii = ncol >> 1;
                    float sn, cs; sincosf(pos * g_theta[ii], &sn, &cs);
                    g_XQf[(long)m * FOLD + ii] = xe * (cs + sn) + xo * (cs - sn);
                } else if (region == 1) {
                    const int kk = ncol - 1024;
                    float sn, cs; sincosf(pos * g_theta[512 + (kk >> 1)], &sn, &cs);
                    const float k0v = xe * cs - xo * sn;
                    const float k1v = xe * sn + xo * cs;
                    float h0, l0, h1, l1;
                    split_hl_f(k0v, h0, l0);
                    split_hl_f(k1v, h1, l1);
                    *(float4*)(g_XKHL + (long)m * (FOLD * 2) + 2 * kk) =
                        make_float4(h0, l0, h1, l1);
                } else {
                    const int vv = ncol - 1536;
                    *(float2*)(g_XV + (long)m * FOLD + vv) = make_float2(xe, xo);
                }
            }
        }
    }
}

// ---------------------------------------------------------------------------
// Kernel 2: prep — fold Wo pairwise + RoPE theta table (f64-accurate)
// ---------------------------------------------------------------------------
__global__ void prep(const float* __restrict__ Wo)
{
    const int idx = blockIdx.x * 256 + threadIdx.x;   // < 512*1024
    const int k = idx >> 10, n = idx & 1023;
    g_WoF[idx] = Wo[(2 * k) * IN_D + n] + Wo[(2 * k + 1) * IN_D + n];
    if (idx < 512)
        g_theta[idx] = (float)pow(10000.0, -(double)(2 * idx) / 1024.0);
    else if (idx < 768)
        g_theta[idx] = (float)pow(10000.0, -(double)(2 * (idx - 512)) / 512.0);
}

// ---------------------------------------------------------------------------
// Kernel 3: tensor-core flash attention, folded head dim 32.
// K arrives pre-split INTERLEAVED (hi,lo): QK inner loop is 2 LDS.64 per
// fragment pair, zero split ALU. Row stride 72 floats (36 float2): bank =
// (8tq+2tr)%32; colliding pairs (tq,tq+4) fall in different 64-bit phases
// -> conflict-free. V stride 40 (proven). cp.async double-buffered.
// grid (SEQ/128, BATCH*HEADS), 256 threads, 2 CTAs/SM, dyn smem 57344 B.
// ---------------------------------------------------------------------------
#define K_STRF 72                          // K row stride in floats (36 float2)
#define K_TILE (64 * K_STRF)               // 4608 floats
#define V_STR  40
#define V_TILE (64 * V_STR)                // 2560 floats
#define ATT_SMEM ((2 * K_TILE + 2 * V_TILE) * 4)   // 57344 B

__global__ __launch_bounds__(256, 2) void attn_mma()
{
    extern __shared__ float asmem[];
    float* KHL = asmem;                    // [2][K_TILE]
    float* VV  = asmem + 2 * K_TILE;       // [2][V_TILE]

    const int tid = threadIdx.x;
    const int wid = tid >> 5, lane = tid & 31;
    const int tq = lane >> 2, tr = lane & 3;
    const int h = blockIdx.y & (HEADS - 1);
    const int b = blockIdx.y >> 4;
    const int hoff = h * 32;
    const long kvbase = (long)b * SEQ;
    const int row0 = blockIdx.x * 128 + wid * 16 + tq;
    const long gq = (kvbase + row0) * FOLD + hoff;

    // ones-column for the denominator (V cols 32..39; cp.async writes 0..31)
    if (tid < 64) {
        #pragma unroll
        for (int bb = 0; bb < 2; bb++) {
            VV[bb * V_TILE + tid * V_STR + 32] = 1.0f;
            #pragma unroll
            for (int z = 33; z < 40; z++) VV[bb * V_TILE + tid * V_STR + z] = 0.0f;
        }
    }

    // Q fragments (persistent, trunc hi/lo split), pre-scaled by 0.5*log2(e)
    const float QS = 0.72134752044448170368f;
    uint32_t qh[4][4], ql[4][4];
    #pragma unroll
    for (int ks = 0; ks < 4; ks++) {
        const int d = ks * 8 + tr;
        float v[4];
        v[0] = g_XQf[gq + d] * QS;
        v[1] = g_XQf[gq + 8 * FOLD + d] * QS;
        v[2] = g_XQf[gq + d + 4] * QS;
        v[3] = g_XQf[gq + 8 * FOLD + d + 4] * QS;
        #pragma unroll
        for (int j = 0; j < 4; j++) split_hl(v[j], qh[ks][j], ql[ks][j]);
    }

    float c[5][4];
    #pragma unroll
    for (int i = 0; i < 5; i++)
        #pragma unroll
        for (int j = 0; j < 4; j++) c[i][j] = 0.f;

    // loader mapping: 4 threads per key row; K row payload = 64 floats (4x16B
    // per thread), V row payload = 32 floats (2x16B per thread covers 8).
    const int lr = tid >> 2, lc = tid & 3;
    const uint32_t khlu = smem_u32(KHL);
    const uint32_t vvu  = smem_u32(VV);

    auto load_kv = [&](int buf, int t0) {
        const float* kp = g_XKHL + (kvbase + t0 + lr) * (FOLD * 2) + hoff * 2 + lc * 16;
        const float* vp = g_XV   + (kvbase + t0 + lr) * FOLD + hoff + lc * 8;
        const uint32_t koff = (uint32_t)(buf * K_TILE + lr * K_STRF + lc * 16) * 4;
        const uint32_t voff = (uint32_t)(buf * V_TILE + lr * V_STR  + lc * 8) * 4;
        CPA16(koff + khlu,      kp);
        CPA16(koff + khlu + 16, kp + 4);
        CPA16(koff + khlu + 32, kp + 8);
        CPA16(koff + khlu + 48, kp + 12);
        CPA16(voff + vvu,      vp);
        CPA16(voff + vvu + 16, vp + 4);
        CP_COMMIT();
    };

    load_kv(0, 0);
    const int nit = SEQ / 64;
    for (int it = 0; it < nit; it++) {
        CP_WAIT0();
        __syncthreads();
        if (it + 1 < nit) load_kv((it + 1) & 1, (it + 1) * 64);

        const float2* K2 = (const float2*)(KHL + (it & 1) * K_TILE);
        const float*  Vb = VV + (it & 1) * V_TILE;

        // ---- S = Qf @ K^T (3xTF32), log2 domain; K pre-split interleaved ----
        float s[8][4];
        #pragma unroll
        for (int nt = 0; nt < 8; nt++)
            #pragma unroll
            for (int j = 0; j < 4; j++) s[nt][j] = 0.f;

        #pragma unroll
        for (int ks = 0; ks < 4; ks++) {
            #pragma unroll
            for (int nt = 0; nt < 8; nt++) {
                const int ri = (nt * 8 + tq) * 36 + ks * 8 + tr;   // float2 units
                const float2 u0 = K2[ri];
                const float2 u1 = K2[ri + 4];
                uint32_t bh[2] = { __float_as_uint(u0.x), __float_as_uint(u1.x) };
                uint32_t bl[2] = { __float_as_uint(u0.y), __float_as_uint(u1.y) };
                mma_tf32(s[nt], ql[ks], bh);
                mma_tf32(s[nt], qh[ks], bl);
                mma_tf32(s[nt], qh[ks], bh);
            }
        }

        // ---- p = 2^s on the FMA pipe ----
        #pragma unroll
        for (int nt = 0; nt < 8; nt++)
            #pragma unroll
            for (int j = 0; j < 4; j++) s[nt][j] = exp2fast(s[nt][j]);

        // ---- ctx += P @ [V | 1] (1x tf32; raw fp32 P bits) ----
        const int sl = (lane & 28) | ((lane >> 1) & 1);
        const bool odd = lane & 1;
        #pragma unroll
        for (int ks = 0; ks < 8; ks++) {
            float x0 = __shfl_sync(0xffffffffu, s[ks][0], sl);
            float x1 = __shfl_sync(0xffffffffu, s[ks][1], sl);
            float x2 = __shfl_sync(0xffffffffu, s[ks][2], sl);
            float x3 = __shfl_sync(0xffffffffu, s[ks][3], sl);
            float y0 = __shfl_sync(0xffffffffu, s[ks][0], sl + 2);
            float y1 = __shfl_sync(0xffffffffu, s[ks][1], sl + 2);
            float y2 = __shfl_sync(0xffffffffu, s[ks][2], sl + 2);
            float y3 = __shfl_sync(0xffffffffu, s[ks][3], sl + 2);
            uint32_t a[4];
            a[0] = __float_as_uint(odd ? x1 : x0);
            a[1] = __float_as_uint(odd ? x3 : x2);
            a[2] = __float_as_uint(odd ? y1 : y0);
            a[3] = __float_as_uint(odd ? y3 : y2);
            #pragma unroll
            for (int nt = 0; nt < 5; nt++) {
                const int vi = (ks * 8 + tr) * V_STR + nt * 8 + tq;
                uint32_t bv[2] = { ((const uint32_t*)Vb)[vi],
                                   ((const uint32_t*)Vb)[vi + 4 * V_STR] };
                mma_tf32(c[nt], a, bv);
            }
        }
        __syncthreads();   // compute(it) done before next iter's loads overwrite
    }

    // ---- normalize and write ----
    const float l0 = __shfl_sync(0xffffffffu, c[4][0], lane & 28);
    const float l1 = __shfl_sync(0xffffffffu, c[4][2], lane & 28);
    const float i0 = 1.0f / l0, i1 = 1.0f / l1;
    #pragma unroll
    for (int nt = 0; nt < 4; nt++) {
        const int col = nt * 8 + 2 * tr;
        *(float2*)(g_CTX + gq + col) =
            make_float2(c[nt][0] * i0, c[nt][1] * i0);
        *(float2*)(g_CTX + gq + 8 * FOLD + col) =
            make_float2(c[nt][2] * i1, c[nt][3] * i1);
    }
}

// ---------------------------------------------------------------------------
// Kernel 4: output projection CTX @ WoF (3xTF32)
// ---------------------------------------------------------------------------
__global__ __launch_bounds__(256) void gemm_out(float* __restrict__ C)
{
    extern __shared__ float sm[];
    uint32_t smb = smem_u32(sm);

    const int tid = threadIdx.x;
    const int wid = tid >> 5, lane = tid & 31;
    const int wm = wid & 1, wn = wid >> 1;
    const int tq = lane >> 2, tr = lane & 3;
    const int m_base = blockIdx.y * 128;
    const int n_base = blockIdx.x * 128;

    float c[4][4][4];
    #pragma unroll
    for (int i = 0; i < 4; i++)
        #pragma unroll
        for (int j = 0; j < 4; j++)
            #pragma unroll
            for (int r = 0; r < 4; r++) c[i][j][r] = 0.f;

    gemm_mainloop(sm, smb, g_CTX + (long)m_base * FOLD, FOLD,
                  g_WoF + n_base, IN_D, FOLD, tid, c);

    #pragma unroll
    for (int mi = 0; mi < 4; mi++)
        #pragma unroll
        for (int h = 0; h < 2; h++) {
            const int m = m_base + wm * 64 + mi * 16 + tq + h * 8;
            #pragma unroll
            for (int ni = 0; ni < 4; ni++) {
                const int col = n_base + wn * 32 + ni * 8 + 2 * tr;
                *(float2*)(C + (long)m * IN_D + col) =
                    make_float2(c[mi][ni][2 * h], c[mi][ni][2 * h + 1]);
            }
        }
}

// ---------------------------------------------------------------------------
extern "C" void kernel_launch(void* const* d_in, const int* in_sizes, int n_in,
                              void* d_out, int out_size)
{
    const float* q  = (const float*)d_in[0];
    const float* Wq = (const float*)d_in[1];
    const float* Wk = (const float*)d_in[2];
    const float* Wv = (const float*)d_in[3];
    const float* Wo = (const float*)d_in[4];

    static int configured = 0;
    if (!configured) {
        cudaFuncSetAttribute(gemm_qkv, cudaFuncAttributeMaxDynamicSharedMemorySize, GSMEM_BYTES);
        cudaFuncSetAttribute(gemm_out, cudaFuncAttributeMaxDynamicSharedMemorySize, GSMEM_BYTES);
        cudaFuncSetAttribute(attn_mma, cudaFuncAttributeMaxDynamicSharedMemorySize, ATT_SMEM);
        configured = 1;
    }

    prep    <<<2048, 256>>>(Wo);                                     // WoF + theta
    gemm_qkv<<<dim3(16, 32), 256, GSMEM_BYTES>>>(q, Wq, Wk, Wv);     // 3xTF32 + rope
    attn_mma<<<dim3(SEQ / 128, BATCH * HEADS), 256, ATT_SMEM>>>();   // tensor-core attn
    gemm_out<<<dim3(8, 32), 256, GSMEM_BYTES>>>((float*)d_out);      // 3xTF32
}

// round 16
// speedup vs baseline: 1.1187x; 1.1187x over previous
#include <cuda_runtime.h>
#include <math.h>
#include <cstdint>

// Problem constants
#define BATCH   2
#define SEQ     2048
#define HEADS   16
#define IN_D    1024
#define MROWS   (BATCH*SEQ)       // 4096
#define FOLD    512               // folded width

// Scratch (device globals; no allocation allowed)
__device__ __align__(256) float g_XQf[MROWS*FOLD];   // folded+rope'd Q  [4096,512]
__device__ __align__(256) float g_XK [MROWS*FOLD];   // rope'd K         [4096,512]
__device__ __align__(256) float g_XV [MROWS*FOLD];   // V                [4096,512]
__device__ __align__(256) float g_CTX[MROWS*FOLD];   // attention ctx    [4096,512]
__device__ __align__(256) float g_WoF[FOLD*IN_D];    // folded Wo        [512,1024]
__device__ float g_theta[768];                       // [0,512): Q pair thetas, [512,768): K

// ---------------------------------------------------------------------------
// Helpers
// ---------------------------------------------------------------------------
__device__ __forceinline__ uint32_t smem_u32(const void* p) {
    uint32_t a;
    asm("{ .reg .u64 t; cvta.to.shared.u64 t, %1; cvt.u32.u64 %0, t; }" : "=r"(a) : "l"(p));
    return a;
}

// Truncation hi/lo split for 3xTF32 (proven numerics).
__device__ __forceinline__ void split_hl(float x, uint32_t& h, uint32_t& l) {
    h = __float_as_uint(x) & 0xFFFFE000u;
    l = __float_as_uint(x - __uint_as_float(h));
}

__device__ __forceinline__ void mma_tf32(float* d, const uint32_t* a, const uint32_t* b) {
    asm volatile(
        "mma.sync.aligned.m16n8k8.row.col.f32.tf32.tf32.f32 "
        "{%0,%1,%2,%3}, {%4,%5,%6,%7}, {%8,%9}, {%0,%1,%2,%3};"
        : "+f"(d[0]), "+f"(d[1]), "+f"(d[2]), "+f"(d[3])
        : "r"(a[0]), "r"(a[1]), "r"(a[2]), "r"(a[3]), "r"(b[0]), "r"(b[1]));
}

// 2^t via MUFU (one instruction; frees ~7 FMA-pipe issue slots per value vs
// the polynomial exp2fast). ~2 ulp accuracy — same class as the polynomial.
__device__ __forceinline__ float ex2_mufu(float t) {
    float r;
    asm("ex2.approx.f32 %0, %1;" : "=f"(r) : "f"(t));
    return r;
}

// cp.async (LDGSTS) primitives
#define CPA16(dst, src) \
    asm volatile("cp.async.cg.shared.global [%0], [%1], 16;" :: "r"(dst), "l"(src) : "memory")
#define CP_COMMIT() asm volatile("cp.async.commit_group;" ::: "memory")
#define CP_WAIT1()  asm volatile("cp.async.wait_group 1;" ::: "memory")
#define CP_WAIT0()  asm volatile("cp.async.wait_group 0;" ::: "memory")

// Smem strides (floats) chosen for conflict-free fragment LDS:
//   A[m][k]: stride 36 -> bank(m,k) = (4m+k)%32, distinct over the 8x4 lane grid
//   B[k][n]: stride 136 -> bank(k,n) = (8k+n)%32, distinct over the 4x8 lane grid
#define A_STR 36
#define B_STR 136
#define A_ELEMS (128 * A_STR)
#define B_ELEMS (32 * B_STR)
#define BUF_FLOATS (A_ELEMS + B_ELEMS)
#define GSMEM_BYTES (2 * BUF_FLOATS * 4)   // raw fp32, double-buffered: 71680 B

// ---------------------------------------------------------------------------
// 3xTF32 tile GEMM mainloop — EXACT R9 measured-best scheme (WAIT1 prefetch).
// Raw fp32 tiles via cp.async double buffering, hi/lo split in registers.
// CTA tile 128x128, BK=32, 256 threads (8 warps 2x4), warp tile 64x32.
// ---------------------------------------------------------------------------
__device__ __forceinline__ void gemm_mainloop(
    float* sm, uint32_t smb,
    const float* __restrict__ A, int lda,
    const float* __restrict__ B, int ldb,
    int nk, int tid, float c[4][4][4])
{
    const int wid = tid >> 5, lane = tid & 31;
    const int wm = wid & 1, wn = wid >> 1;
    const int tq = lane >> 2, tr = lane & 3;
    const int nit = nk / 32;

    auto load_tile = [&](int buf, int k0) {
        uint32_t as = smb + buf * (BUF_FLOATS * 4);
        uint32_t bs = as + A_ELEMS * 4;
        #pragma unroll
        for (int i = 0; i < 4; i++) {
            int e = i * 256 + tid;
            int r = e >> 3, c4 = e & 7;
            CPA16(as + (uint32_t)(r * A_STR + c4 * 4) * 4,
                  A + (long)r * lda + k0 + c4 * 4);
        }
        #pragma unroll
        for (int i = 0; i < 4; i++) {
            int e = i * 256 + tid;
            int kr = e >> 5, c4 = e & 31;
            CPA16(bs + (uint32_t)(kr * B_STR + c4 * 4) * 4,
                  B + (long)(k0 + kr) * ldb + c4 * 4);
        }
        CP_COMMIT();
    };

    load_tile(0, 0);
    for (int it = 0; it < nit; it++) {
        if (it + 1 < nit) { load_tile((it + 1) & 1, (it + 1) * 32); CP_WAIT1(); }
        else              { CP_WAIT0(); }
        __syncthreads();

        const float* As = sm + (it & 1) * BUF_FLOATS;
        const float* Bs = As + A_ELEMS;

        #pragma unroll
        for (int ks = 0; ks < 4; ks++) {
            uint32_t ah[4][4], al[4][4], bh[4][2], bl[4][2];
            #pragma unroll
            for (int mi = 0; mi < 4; mi++) {
                int base = (wm * 64 + mi * 16 + tq) * A_STR + ks * 8 + tr;
                split_hl(As[base],                 ah[mi][0], al[mi][0]);
                split_hl(As[base + 8 * A_STR],     ah[mi][1], al[mi][1]);
                split_hl(As[base + 4],             ah[mi][2], al[mi][2]);
                split_hl(As[base + 8 * A_STR + 4], ah[mi][3], al[mi][3]);
            }
            #pragma unroll
            for (int ni = 0; ni < 4; ni++) {
                int base = (ks * 8 + tr) * B_STR + wn * 32 + ni * 8 + tq;
                split_hl(Bs[base],             bh[ni][0], bl[ni][0]);
                split_hl(Bs[base + 4 * B_STR], bh[ni][1], bl[ni][1]);
            }
            #pragma unroll
            for (int mi = 0; mi < 4; mi++)
                #pragma unroll
                for (int ni = 0; ni < 4; ni++) {
                    mma_tf32(c[mi][ni], al[mi], bh[ni]);
                    mma_tf32(c[mi][ni], ah[mi], bl[ni]);
                    mma_tf32(c[mi][ni], ah[mi], bh[ni]);
                }
        }
        __syncthreads();
    }
}

// ---------------------------------------------------------------------------
// Kernel 1: QKV projection (3xTF32) + RoPE/fold on fragments (R9-exact)
// ---------------------------------------------------------------------------
__global__ __launch_bounds__(256) void gemm_qkv(
    const float* __restrict__ A,
    const float* __restrict__ Wq,
    const float* __restrict__ Wk,
    const float* __restrict__ Wv)
{
    extern __shared__ float sm[];
    uint32_t smb = smem_u32(sm);

    const int tid = threadIdx.x;
    const int wid = tid >> 5, lane = tid & 31;
    const int wm = wid & 1, wn = wid >> 1;
    const int tq = lane >> 2, tr = lane & 3;
    const int m_base = blockIdx.y * 128;
    const int n_base = blockIdx.x * 128;

    const float* Bm; int ldb, region;
    if (n_base < 1024)      { Bm = Wq + n_base;          ldb = 1024; region = 0; }
    else if (n_base < 1536) { Bm = Wk + (n_base - 1024); ldb = 512;  region = 1; }
    else                    { Bm = Wv + (n_base - 1536); ldb = 512;  region = 2; }

    float c[4][4][4];
    #pragma unroll
    for (int i = 0; i < 4; i++)
        #pragma unroll
        for (int j = 0; j < 4; j++)
            #pragma unroll
            for (int r = 0; r < 4; r++) c[i][j][r] = 0.f;

    gemm_mainloop(sm, smb, A + (long)m_base * IN_D, IN_D, Bm, ldb, IN_D, tid, c);

    #pragma unroll
    for (int mi = 0; mi < 4; mi++) {
        #pragma unroll
        for (int h = 0; h < 2; h++) {
            const int m = m_base + wm * 64 + mi * 16 + tq + h * 8;
            const float pos = (float)((m & (SEQ - 1)) + 1);
            #pragma unroll
            for (int ni = 0; ni < 4; ni++) {
                const float xe = c[mi][ni][2 * h];
                const float xo = c[mi][ni][2 * h + 1];
                const int ncol = n_base + wn * 32 + ni * 8 + 2 * tr;
                if (region == 0) {
                    const int ii = ncol >> 1;
                    float sn, cs; sincosf(pos * g_theta[ii], &sn, &cs);
                    g_XQf[(long)m * FOLD + ii] = xe * (cs + sn) + xo * (cs - sn);
                } else if (region == 1) {
                    const int kk = ncol - 1024;
                    float sn, cs; sincosf(pos * g_theta[512 + (kk >> 1)], &sn, &cs);
                    *(float2*)(g_XK + (long)m * FOLD + kk) =
                        make_float2(xe * cs - xo * sn, xe * sn + xo * cs);
                } else {
                    const int vv = ncol - 1536;
                    *(float2*)(g_XV + (long)m * FOLD + vv) = make_float2(xe, xo);
                }
            }
        }
    }
}

// ---------------------------------------------------------------------------
// Kernel 2: prep — fold Wo pairwise + RoPE theta table (R9-exact)
// ---------------------------------------------------------------------------
__global__ void prep(const float* __restrict__ Wo)
{
    const int idx = blockIdx.x * 256 + threadIdx.x;
    const int k = idx >> 10, n = idx & 1023;
    g_WoF[idx] = Wo[(2 * k) * IN_D + n] + Wo[(2 * k + 1) * IN_D + n];
    if (idx < 512)
        g_theta[idx] = (float)pow(10000.0, -(double)(2 * idx) / 1024.0);
    else if (idx < 768)
        g_theta[idx] = (float)pow(10000.0, -(double)(2 * (idx - 512)) / 512.0);
}

// ---------------------------------------------------------------------------
// Kernel 3: tensor-core flash attention (R9-exact EXCEPT exp: MUFU ex2).
// QK^T 3xTF32 in log2 domain; PV 1x tf32 with denominator through the same
// MMA (ones-column; truncation bias cancels).
// grid (SEQ/128, BATCH*HEADS), 256 threads, 2 CTAs/SM.
// ---------------------------------------------------------------------------
#define KV_STR 40   // conflict-free row stride

__global__ __launch_bounds__(256, 2) void attn_mma()
{
    __shared__ float Kr[2][64 * KV_STR];
    __shared__ float Vv[2][64 * KV_STR];

    const int tid = threadIdx.x;
    const int wid = tid >> 5, lane = tid & 31;
    const int tq = lane >> 2, tr = lane & 3;
    const int h = blockIdx.y & (HEADS - 1);
    const int b = blockIdx.y >> 4;
    const int hoff = h * 32;
    const long kvbase = (long)b * SEQ;
    const int row0 = blockIdx.x * 128 + wid * 16 + tq;
    const long gq = (kvbase + row0) * FOLD + hoff;

    // ones-column for the denominator (cols 32..39; cp.async writes only 0..31)
    if (tid < 64) {
        #pragma unroll
        for (int bb = 0; bb < 2; bb++) {
            Vv[bb][tid * KV_STR + 32] = 1.0f;
            #pragma unroll
            for (int z = 33; z < 40; z++) Vv[bb][tid * KV_STR + z] = 0.0f;
        }
    }

    // Q fragments (persistent, trunc hi/lo split), pre-scaled by 0.5*log2(e)
    const float QS = 0.72134752044448170368f;
    uint32_t qh[4][4], ql[4][4];
    #pragma unroll
    for (int ks = 0; ks < 4; ks++) {
        const int d = ks * 8 + tr;
        float v[4];
        v[0] = g_XQf[gq + d] * QS;
        v[1] = g_XQf[gq + 8 * FOLD + d] * QS;
        v[2] = g_XQf[gq + d + 4] * QS;
        v[3] = g_XQf[gq + 8 * FOLD + d + 4] * QS;
        #pragma unroll
        for (int j = 0; j < 4; j++) split_hl(v[j], qh[ks][j], ql[ks][j]);
    }

    float c[5][4];
    #pragma unroll
    for (int i = 0; i < 5; i++)
        #pragma unroll
        for (int j = 0; j < 4; j++) c[i][j] = 0.f;

    // loader mapping: 4 threads per key row, 8 dims each
    const int lr = tid >> 2, lc = (tid & 3) * 8;
    const uint32_t kbu = smem_u32(&Kr[0][0]);
    const uint32_t vbu = smem_u32(&Vv[0][0]);

    auto load_kv = [&](int buf, int t0) {
        const float* kp = g_XK + (kvbase + t0 + lr) * FOLD + hoff + lc;
        const float* vp = g_XV + (kvbase + t0 + lr) * FOLD + hoff + lc;
        const uint32_t off = (uint32_t)(buf * 64 * KV_STR + lr * KV_STR + lc) * 4;
        CPA16(kbu + off, kp);  CPA16(kbu + off + 16, kp + 4);
        CPA16(vbu + off, vp);  CPA16(vbu + off + 16, vp + 4);
        CP_COMMIT();
    };

    load_kv(0, 0);
    const int nit = SEQ / 64;
    for (int it = 0; it < nit; it++) {
        if (it + 1 < nit) { load_kv((it + 1) & 1, (it + 1) * 64); CP_WAIT1(); }
        else              { CP_WAIT0(); }
        __syncthreads();

        const float* Kb = Kr[it & 1];
        const float* Vb = Vv[it & 1];

        // ---- S = Qf @ K^T (3xTF32), log2 domain ----
        float s[8][4];
        #pragma unroll
        for (int nt = 0; nt < 8; nt++)
            #pragma unroll
            for (int j = 0; j < 4; j++) s[nt][j] = 0.f;

        #pragma unroll
        for (int ks = 0; ks < 4; ks++) {
            #pragma unroll
            for (int nt = 0; nt < 8; nt++) {
                const int bi = (nt * 8 + tq) * KV_STR + ks * 8 + tr;
                uint32_t bh[2], bl[2];
                split_hl(Kb[bi],     bh[0], bl[0]);
                split_hl(Kb[bi + 4], bh[1], bl[1]);
                mma_tf32(s[nt], ql[ks], bh);
                mma_tf32(s[nt], qh[ks], bl);
                mma_tf32(s[nt], qh[ks], bh);
            }
        }

        // ---- p = 2^s via MUFU (single instruction per value) ----
        #pragma unroll
        for (int nt = 0; nt < 8; nt++)
            #pragma unroll
            for (int j = 0; j < 4; j++) s[nt][j] = ex2_mufu(s[nt][j]);

        // ---- ctx += P @ [V | 1] (1x tf32; raw fp32 P bits) ----
        const int sl = (lane & 28) | ((lane >> 1) & 1);
        const bool odd = lane & 1;
        #pragma unroll
        for (int ks = 0; ks < 8; ks++) {
            float x0 = __shfl_sync(0xffffffffu, s[ks][0], sl);
            float x1 = __shfl_sync(0xffffffffu, s[ks][1], sl);
            float x2 = __shfl_sync(0xffffffffu, s[ks][2], sl);
            float x3 = __shfl_sync(0xffffffffu, s[ks][3], sl);
            float y0 = __shfl_sync(0xffffffffu, s[ks][0], sl + 2);
            float y1 = __shfl_sync(0xffffffffu, s[ks][1], sl + 2);
            float y2 = __shfl_sync(0xffffffffu, s[ks][2], sl + 2);
            float y3 = __shfl_sync(0xffffffffu, s[ks][3], sl + 2);
            uint32_t a[4];
            a[0] = __float_as_uint(odd ? x1 : x0);
            a[1] = __float_as_uint(odd ? x3 : x2);
            a[2] = __float_as_uint(odd ? y1 : y0);
            a[3] = __float_as_uint(odd ? y3 : y2);
            #pragma unroll
            for (int nt = 0; nt < 5; nt++) {
                const int vi = (ks * 8 + tr) * KV_STR + nt * 8 + tq;
                uint32_t bv[2] = { ((const uint32_t*)Vb)[vi],
                                   ((const uint32_t*)Vb)[vi + 4 * KV_STR] };
                mma_tf32(c[nt], a, bv);
            }
        }
        __syncthreads();
    }

    // ---- normalize and write ----
    const float l0 = __shfl_sync(0xffffffffu, c[4][0], lane & 28);
    const float l1 = __shfl_sync(0xffffffffu, c[4][2], lane & 28);
    const float i0 = 1.0f / l0, i1 = 1.0f / l1;
    #pragma unroll
    for (int nt = 0; nt < 4; nt++) {
        const int col = nt * 8 + 2 * tr;
        *(float2*)(g_CTX + gq + col) =
            make_float2(c[nt][0] * i0, c[nt][1] * i0);
        *(float2*)(g_CTX + gq + 8 * FOLD + col) =
            make_float2(c[nt][2] * i1, c[nt][3] * i1);
    }
}

// ---------------------------------------------------------------------------
// Kernel 4: output projection CTX @ WoF (3xTF32, R9-exact)
// ---------------------------------------------------------------------------
__global__ __launch_bounds__(256) void gemm_out(float* __restrict__ C)
{
    extern __shared__ float sm[];
    uint32_t smb = smem_u32(sm);

    const int tid = threadIdx.x;
    const int wid = tid >> 5, lane = tid & 31;
    const int wm = wid & 1, wn = wid >> 1;
    const int tq = lane >> 2, tr = lane & 3;
    const int m_base = blockIdx.y * 128;
    const int n_base = blockIdx.x * 128;

    float c[4][4][4];
    #pragma unroll
    for (int i = 0; i < 4; i++)
        #pragma unroll
        for (int j = 0; j < 4; j++)
            #pragma unroll
            for (int r = 0; r < 4; r++) c[i][j][r] = 0.f;

    gemm_mainloop(sm, smb, g_CTX + (long)m_base * FOLD, FOLD,
                  g_WoF + n_base, IN_D, FOLD, tid, c);

    #pragma unroll
    for (int mi = 0; mi < 4; mi++)
        #pragma unroll
        for (int h = 0; h < 2; h++) {
            const int m = m_base + wm * 64 + mi * 16 + tq + h * 8;
            #pragma unroll
            for (int ni = 0; ni < 4; ni++) {
                const int col = n_base + wn * 32 + ni * 8 + 2 * tr;
                *(float2*)(C + (long)m * IN_D + col) =
                    make_float2(c[mi][ni][2 * h], c[mi][ni][2 * h + 1]);
            }
        }
}

// ---------------------------------------------------------------------------
extern "C" void kernel_launch(void* const* d_in, const int* in_sizes, int n_in,
                              void* d_out, int out_size)
{
    const float* q  = (const float*)d_in[0];
    const float* Wq = (const float*)d_in[1];
    const float* Wk = (const float*)d_in[2];
    const float* Wv = (const float*)d_in[3];
    const float* Wo = (const float*)d_in[4];

    static int configured = 0;
    if (!configured) {
        cudaFuncSetAttribute(gemm_qkv, cudaFuncAttributeMaxDynamicSharedMemorySize, GSMEM_BYTES);
        cudaFuncSetAttribute(gemm_out, cudaFuncAttributeMaxDynamicSharedMemorySize, GSMEM_BYTES);
        configured = 1;
    }

    prep    <<<2048, 256>>>(Wo);                                    // WoF + theta table
    gemm_qkv<<<dim3(16, 32), 256, GSMEM_BYTES>>>(q, Wq, Wk, Wv);    // 3xTF32 + rope
    attn_mma<<<dim3(SEQ / 128, BATCH * HEADS), 256>>>();            // tensor-core flash attn
    gemm_out<<<dim3(8, 32), 256, GSMEM_BYTES>>>((float*)d_out);     // 3xTF32
}